// round 2
// baseline (speedup 1.0000x reference)
#include <cuda_runtime.h>
#include <math.h>

// ---------------------------------------------------------------------------
// Problem constants
// ---------------------------------------------------------------------------
#define BATCH 8
#define CIN   256
#define EMB   512
#define HW    48
#define NPIX  (HW*HW)          // 2304
#define KDIM  (CIN*9)          // 2304  (im2col K)

// ---------------------------------------------------------------------------
// Scratch (static __device__ globals; no allocation allowed)  ~358 MB total
// ---------------------------------------------------------------------------
__device__ float g_q   [(size_t)BATCH * EMB  * NPIX];   // [B][512][2304]
__device__ float g_k   [(size_t)BATCH * EMB  * NPIX];
__device__ float g_v   [(size_t)BATCH * EMB  * NPIX];
__device__ float g_vT  [(size_t)BATCH * NPIX * EMB ];   // [B][2304][512]
__device__ float g_att [(size_t)BATCH * NPIX * NPIX];   // [B][2304][2304]
__device__ float g_outT[(size_t)BATCH * NPIX * EMB ];   // [B][2304][512]

// ---------------------------------------------------------------------------
// Fused conv-as-GEMM for q,k,v.  C[e][n] = sum_k W[e][k] * col(k, n) + bias[e]
// col(k,n) materialized on the fly from feat (3x3, pad 1).
// Grid: (NPIX/128, 3*EMB/128, BATCH). blockIdx.y>>2 selects which conv.
// 128x128 tile, BK=8, 256 threads, 8x8 microtile.
// ---------------------------------------------------------------------------
__global__ __launch_bounds__(256)
void conv_gemm_qkv(const float* __restrict__ feat,
                   const float* __restrict__ Wq, const float* __restrict__ Wk,
                   const float* __restrict__ Wv,
                   const float* __restrict__ bq, const float* __restrict__ bk,
                   const float* __restrict__ bv,
                   float* __restrict__ q, float* __restrict__ k,
                   float* __restrict__ v)
{
    __shared__ __align__(16) float As[8][128];
    __shared__ __align__(16) float Bs[8][128];

    const int b     = blockIdx.z;
    const int which = blockIdx.y >> 2;          // 0=q 1=k 2=v
    const int bm    = (blockIdx.y & 3) * 128;   // output channel tile
    const int bn    = blockIdx.x * 128;         // pixel tile

    const float* A    = (which == 0) ? Wq : (which == 1) ? Wk : Wv;
    const float* bias = (which == 0) ? bq : (which == 1) ? bk : bv;
    float*       C    = ((which == 0) ? q : (which == 1) ? k : v)
                        + (long)b * EMB * NPIX;
    const float* fb   = feat + (long)b * CIN * HW * HW;

    const int tid = threadIdx.x;
    const int tx = tid & 15, ty = tid >> 4;
    const int row0 = ty * 8, col0 = tx * 8;

    float acc[8][8];
#pragma unroll
    for (int i = 0; i < 8; i++)
#pragma unroll
        for (int j = 0; j < 8; j++) acc[i][j] = 0.f;

    // A-load mapping: thread -> (row am, 4 consecutive k)
    const int am  = tid >> 1;
    const int ak0 = (tid & 1) * 4;
    // B-load mapping: thread -> (k row bk, 4 consecutive pixels)
    const int bkr = tid >> 5;                   // 0..7
    const int bn0 = (tid & 31) * 4;             // 0..124, 4-aligned

    // pixel coords for this thread's B row (fixed across k loop)
    const int npx = bn + bn0;                   // 4-aligned; 48 % 4 == 0
    const int ph  = npx / HW;
    const int pw  = npx % HW;                   // pw..pw+3 same image row

    for (int k0 = 0; k0 < KDIM; k0 += 8) {
        // ---- load A tile (coalesced: consecutive tid -> consecutive k) ----
#pragma unroll
        for (int i = 0; i < 4; i++)
            As[ak0 + i][am] = A[(long)(bm + am) * KDIM + (k0 + ak0 + i)];

        // ---- materialize B tile via im2col ----
        {
            const int kk = k0 + bkr;            // im2col row
            const int c  = kk / 9;
            const int k9 = kk - c * 9;
            const int ky = k9 / 3;
            const int kx = k9 - ky * 3;
            const int hs = ph + ky - 1;
            const float* frow = fb + ((long)c * HW + hs) * HW;
            const bool hok = (hs >= 0) & (hs < HW);
#pragma unroll
            for (int i = 0; i < 4; i++) {
                const int ws = pw + i + kx - 1;
                float val = 0.f;
                if (hok && ws >= 0 && ws < HW) val = frow[ws];
                Bs[bkr][bn0 + i] = val;
            }
        }
        __syncthreads();

#pragma unroll
        for (int kk = 0; kk < 8; kk++) {
            float4 a0 = *reinterpret_cast<const float4*>(&As[kk][row0]);
            float4 a1 = *reinterpret_cast<const float4*>(&As[kk][row0 + 4]);
            float4 b0 = *reinterpret_cast<const float4*>(&Bs[kk][col0]);
            float4 b1 = *reinterpret_cast<const float4*>(&Bs[kk][col0 + 4]);
            float ra[8] = {a0.x, a0.y, a0.z, a0.w, a1.x, a1.y, a1.z, a1.w};
            float rb[8] = {b0.x, b0.y, b0.z, b0.w, b1.x, b1.y, b1.z, b1.w};
#pragma unroll
            for (int i = 0; i < 8; i++)
#pragma unroll
                for (int j = 0; j < 8; j++)
                    acc[i][j] += ra[i] * rb[j];
        }
        __syncthreads();
    }

#pragma unroll
    for (int i = 0; i < 8; i++) {
        const float bv_ = bias[bm + row0 + i];
#pragma unroll
        for (int j = 0; j < 8; j++)
            C[(long)(bm + row0 + i) * NPIX + (bn + col0 + j)] = acc[i][j] + bv_;
    }
}

// ---------------------------------------------------------------------------
// Generic strided batched SGEMM: C[b][m][n] = sum_k A(m,k)*B(k,n)
// ---------------------------------------------------------------------------
__global__ __launch_bounds__(256)
void sgemm128(const float* __restrict__ A, long batchA, int sAm, int sAk,
              const float* __restrict__ B, long batchB, int sBk, int sBn,
              float*       __restrict__ C, long batchC,
              int M, int N, int K)
{
    __shared__ __align__(16) float As[8][128];
    __shared__ __align__(16) float Bs[8][128];

    const int bz = blockIdx.z;
    A += (long)bz * batchA;
    B += (long)bz * batchB;
    C += (long)bz * batchC;

    const int bm = blockIdx.y * 128;
    const int bn = blockIdx.x * 128;
    const int tid = threadIdx.x;
    const int tx = tid & 15, ty = tid >> 4;
    const int row0 = ty * 8, col0 = tx * 8;

    float acc[8][8];
#pragma unroll
    for (int i = 0; i < 8; i++)
#pragma unroll
        for (int j = 0; j < 8; j++) acc[i][j] = 0.f;

    const int am  = tid >> 1;
    const int ak0 = (tid & 1) * 4;
    const int bkr = tid >> 5;
    const int bn0 = (tid & 31) * 4;

    for (int k0 = 0; k0 < K; k0 += 8) {
#pragma unroll
        for (int i = 0; i < 4; i++)
            As[ak0 + i][am] = A[(long)(bm + am) * sAm + (long)(k0 + ak0 + i) * sAk];
#pragma unroll
        for (int i = 0; i < 4; i++)
            Bs[bkr][bn0 + i] = B[(long)(k0 + bkr) * sBk + (long)(bn + bn0 + i) * sBn];
        __syncthreads();

#pragma unroll
        for (int kk = 0; kk < 8; kk++) {
            float4 a0 = *reinterpret_cast<const float4*>(&As[kk][row0]);
            float4 a1 = *reinterpret_cast<const float4*>(&As[kk][row0 + 4]);
            float4 b0 = *reinterpret_cast<const float4*>(&Bs[kk][col0]);
            float4 b1 = *reinterpret_cast<const float4*>(&Bs[kk][col0 + 4]);
            float ra[8] = {a0.x, a0.y, a0.z, a0.w, a1.x, a1.y, a1.z, a1.w};
            float rb[8] = {b0.x, b0.y, b0.z, b0.w, b1.x, b1.y, b1.z, b1.w};
#pragma unroll
            for (int i = 0; i < 8; i++)
#pragma unroll
                for (int j = 0; j < 8; j++)
                    acc[i][j] += ra[i] * rb[j];
        }
        __syncthreads();
    }

#pragma unroll
    for (int i = 0; i < 8; i++)
#pragma unroll
        for (int j = 0; j < 8; j++)
            C[(long)(bm + row0 + i) * N + (bn + col0 + j)] = acc[i][j];
}

// ---------------------------------------------------------------------------
// In-place row softmax over the last dim of att[b][i][:]  (NPIX columns)
// ---------------------------------------------------------------------------
__global__ __launch_bounds__(256)
void softmax_rows(float* __restrict__ att)
{
    const long row = blockIdx.x;
    float* p = att + row * NPIX;
    __shared__ float red[256];
    const int t = threadIdx.x;

    float m = -INFINITY;
    for (int j = t; j < NPIX; j += 256) m = fmaxf(m, p[j]);
    red[t] = m; __syncthreads();
    for (int s = 128; s > 0; s >>= 1) {
        if (t < s) red[t] = fmaxf(red[t], red[t + s]);
        __syncthreads();
    }
    m = red[0]; __syncthreads();

    float sum = 0.f;
    for (int j = t; j < NPIX; j += 256) {
        float e = __expf(p[j] - m);
        p[j] = e;
        sum += e;
    }
    red[t] = sum; __syncthreads();
    for (int s = 128; s > 0; s >>= 1) {
        if (t < s) red[t] += red[t + s];
        __syncthreads();
    }
    const float inv = 1.f / red[0];
    for (int j = t; j < NPIX; j += 256) p[j] *= inv;
}

// ---------------------------------------------------------------------------
// Transpose v[b][E][N] -> vT[b][N][E]
// ---------------------------------------------------------------------------
__global__ void transpose_kernel(const float* __restrict__ src, float* __restrict__ dst,
                                 int R, int Ccols)
{
    __shared__ float tile[32][33];
    const int b = blockIdx.z;
    src += (long)b * R * Ccols;
    dst += (long)b * R * Ccols;
    const int c0 = blockIdx.x * 32;
    const int r0 = blockIdx.y * 32;
    const int tx = threadIdx.x, ty = threadIdx.y;   // 32 x 8
#pragma unroll
    for (int i = 0; i < 32; i += 8)
        tile[ty + i][tx] = src[(long)(r0 + ty + i) * Ccols + (c0 + tx)];
    __syncthreads();
#pragma unroll
    for (int i = 0; i < 32; i += 8)
        dst[(long)(c0 + ty + i) * R + (r0 + tx)] = tile[tx][ty + i];
}

// ---------------------------------------------------------------------------
// Epilogue: out[b][e][n] = outT[b][n][e] + v[b][e][n]
// ---------------------------------------------------------------------------
__global__ void epilogue_kernel(const float* __restrict__ outT,
                                const float* __restrict__ v,
                                float* __restrict__ out)
{
    __shared__ float tile[32][33];
    const int b = blockIdx.z;
    const float* src = outT + (long)b * NPIX * EMB;   // [N][E]
    const float* vb  = v    + (long)b * EMB  * NPIX;  // [E][N]
    float*       ob  = out  + (long)b * EMB  * NPIX;  // [E][N]
    const int e0 = blockIdx.x * 32;
    const int n0 = blockIdx.y * 32;
    const int tx = threadIdx.x, ty = threadIdx.y;     // 32 x 8
#pragma unroll
    for (int i = 0; i < 32; i += 8)
        tile[ty + i][tx] = src[(long)(n0 + ty + i) * EMB + (e0 + tx)];
    __syncthreads();
#pragma unroll
    for (int i = 0; i < 32; i += 8) {
        long o = (long)(e0 + ty + i) * NPIX + (n0 + tx);
        ob[o] = tile[tx][ty + i] + vb[o];
    }
}

// ---------------------------------------------------------------------------
// launch
// ---------------------------------------------------------------------------
extern "C" void kernel_launch(void* const* d_in, const int* in_sizes, int n_in,
                              void* d_out, int out_size)
{
    const float* feat = (const float*)d_in[0];
    const float* Wq   = (const float*)d_in[1];
    const float* bq   = (const float*)d_in[2];
    const float* Wk   = (const float*)d_in[3];
    const float* bk   = (const float*)d_in[4];
    const float* Wv   = (const float*)d_in[5];
    const float* bv   = (const float*)d_in[6];
    float* out = (float*)d_out;

    float *q, *k, *v, *vT, *att, *outT;
    cudaGetSymbolAddress((void**)&q,    g_q);
    cudaGetSymbolAddress((void**)&k,    g_k);
    cudaGetSymbolAddress((void**)&v,    g_v);
    cudaGetSymbolAddress((void**)&vT,   g_vT);
    cudaGetSymbolAddress((void**)&att,  g_att);
    cudaGetSymbolAddress((void**)&outT, g_outT);

    const long qkvB = (long)EMB * NPIX;
    const long attB = (long)NPIX * NPIX;

    // 1) fused im2col + conv GEMMs for q,k,v
    {
        dim3 grid(NPIX / 128, 3 * (EMB / 128), BATCH);
        conv_gemm_qkv<<<grid, 256>>>(feat, Wq, Wk, Wv, bq, bk, bv, q, k, v);
    }

    // 2) att[b][i][j] = sum_e q[b][e][i] * k[b][e][j]   (M=N=2304, K=512)
    {
        dim3 grid(NPIX / 128, NPIX / 128, BATCH);
        sgemm128<<<grid, 256>>>(q, qkvB, 1, NPIX,
                                k, qkvB, NPIX, 1,
                                att, attB, NPIX, NPIX, EMB);
    }

    // 3) softmax over j, in place
    softmax_rows<<<BATCH * NPIX, 256>>>(att);

    // 4) vT[b][j][e] = v[b][e][j]
    {
        dim3 grid(NPIX / 32, EMB / 32, BATCH);
        transpose_kernel<<<grid, dim3(32, 8)>>>(v, vT, EMB, NPIX);
    }

    // 5) outT[b][i][e] = sum_j att[b][i][j] * vT[b][j][e]  (M=2304, N=512, K=2304)
    {
        dim3 grid(EMB / 128, NPIX / 128, BATCH);
        sgemm128<<<grid, 256>>>(att, attB, NPIX, 1,
                                vT, qkvB, EMB, 1,
                                outT, qkvB, NPIX, EMB, NPIX);
    }

    // 6) out[b][e][n] = outT[b][n][e] + v[b][e][n]
    {
        dim3 grid(EMB / 32, NPIX / 32, BATCH);
        epilogue_kernel<<<grid, dim3(32, 8)>>>(outT, v, out);
    }
}

// round 5
// speedup vs baseline: 5.8086x; 5.8086x over previous
#include <cuda_runtime.h>
#include <cuda_bf16.h>
#include <math.h>
#include <stdint.h>

// ---------------------------------------------------------------------------
// Problem constants
// ---------------------------------------------------------------------------
#define BATCH 8
#define CIN   256
#define EMB   512
#define HW    48
#define NPIX  2304
#define KDIM  2304

// ---------------------------------------------------------------------------
// Scratch: one big static buffer, carved by offsets. ~297 MB total.
//   COL region aliased: packed colT -> fp32 att -> packed att (in place)
//   QT  region aliased: packed qT   -> fp32 outT (qT dead after logits)
// ---------------------------------------------------------------------------
#define COL_BYTES ((size_t)BATCH * NPIX * KDIM * 4)
#define W_BYTES   ((size_t)EMB * KDIM * 4)
#define QT_BYTES  ((size_t)BATCH * NPIX * EMB * 4)

#define OFF_COL  ((size_t)0)
#define OFF_WQ   (OFF_COL + COL_BYTES)
#define OFF_WK   (OFF_WQ + W_BYTES)
#define OFF_WV   (OFF_WK + W_BYTES)
#define OFF_QT   (OFF_WV + W_BYTES)
#define OFF_KT   (OFF_QT + QT_BYTES)
#define OFF_VP   (OFF_KT + QT_BYTES)
#define SCRATCH_BYTES (OFF_VP + QT_BYTES)

__device__ __align__(1024) unsigned char g_scratch[SCRATCH_BYTES];

// ---------------------------------------------------------------------------
// Helpers
// ---------------------------------------------------------------------------
__device__ __forceinline__ uint32_t smem_u32(const void* p) {
    uint32_t a;
    asm("{ .reg .u64 t; cvta.to.shared.u64 t, %1; cvt.u32.u64 %0, t; }"
        : "=r"(a) : "l"(p));
    return a;
}

// SW64 swizzle: 16B column (bits 4:6) ^= row bits (bits 7:9)
#define SWZ64(o) ((o) ^ (((o) >> 3) & 0x30))

// split fp32 -> packed (bf16hi<<16)|bf16lo
__device__ __forceinline__ uint32_t pack_split(float x) {
    __nv_bfloat16 h = __float2bfloat16(x);
    float hf = __bfloat162float(h);
    __nv_bfloat16 l = __float2bfloat16(x - hf);
    return ((uint32_t)__bfloat16_as_ushort(h) << 16) | (uint32_t)__bfloat16_as_ushort(l);
}
__device__ __forceinline__ float unpack_split(uint32_t p) {
    float hi = __bfloat162float(__ushort_as_bfloat16((unsigned short)(p >> 16)));
    float lo = __bfloat162float(__ushort_as_bfloat16((unsigned short)(p & 0xFFFF)));
    return hi + lo;
}

__device__ __forceinline__ void ldsm4(uint32_t& r0, uint32_t& r1, uint32_t& r2,
                                      uint32_t& r3, uint32_t addr) {
    asm volatile("ldmatrix.sync.aligned.m8n8.x4.shared.b16 {%0,%1,%2,%3}, [%4];"
                 : "=r"(r0), "=r"(r1), "=r"(r2), "=r"(r3) : "r"(addr));
}

__device__ __forceinline__ void mma16816(float* d, const uint32_t* a,
                                         const uint32_t* b) {
    asm volatile(
        "mma.sync.aligned.m16n8k16.row.col.f32.bf16.bf16.f32 "
        "{%0,%1,%2,%3},{%4,%5,%6,%7},{%8,%9},{%0,%1,%2,%3};"
        : "+f"(d[0]), "+f"(d[1]), "+f"(d[2]), "+f"(d[3])
        : "r"(a[0]), "r"(a[1]), "r"(a[2]), "r"(a[3]), "r"(b[0]), "r"(b[1]));
}

__device__ __forceinline__ void sts128(uint32_t addr, uint32_t a, uint32_t b,
                                       uint32_t c, uint32_t d) {
    asm volatile("st.shared.v4.b32 [%0], {%1,%2,%3,%4};"
                 :: "r"(addr), "r"(a), "r"(b), "r"(c), "r"(d) : "memory");
}

// ---------------------------------------------------------------------------
// Converters
// ---------------------------------------------------------------------------
__global__ void pack_weights(const float* __restrict__ Wq, const float* __restrict__ Wk,
                             const float* __restrict__ Wv,
                             uint32_t* __restrict__ oq, uint32_t* __restrict__ ok,
                             uint32_t* __restrict__ ov)
{
    long i = (long)blockIdx.x * 256 + threadIdx.x;
    const long n = (long)EMB * KDIM;
    if (i >= n) return;
    oq[i] = pack_split(Wq[i]);
    ok[i] = pack_split(Wk[i]);
    ov[i] = pack_split(Wv[i]);
}

// colT[b][n][k] = pack(im2col), k = c*9 + ky*3 + kx
__global__ void build_colT(const float* __restrict__ feat, uint32_t* __restrict__ colT)
{
    long idx = (long)blockIdx.x * 256 + threadIdx.x;
    const long total = (long)BATCH * NPIX * KDIM;
    if (idx >= total) return;
    int k = (int)(idx % KDIM);
    long t = idx / KDIM;
    int n = (int)(t % NPIX);
    int b = (int)(t / NPIX);
    int c = k / 9, k9 = k - 9 * c;
    int ky = k9 / 3, kx = k9 - 3 * ky;
    int h = n / HW, w = n - HW * h;
    int hs = h + ky - 1, ws = w + kx - 1;
    float v = 0.f;
    if (hs >= 0 && hs < HW && ws >= 0 && ws < HW)
        v = feat[(((long)b * CIN + c) * HW + hs) * HW + ws];
    colT[idx] = pack_split(v);
}

// ---------------------------------------------------------------------------
// mma.sync GEMM: D[m][n] = sum_k A[m][k] * B[n][k], fp32 accum.
// Packed-split u32 operands, 3-MMA split. 128x128 CTA tile, 8 warps (2x4),
// each warp 64x32. K-chunk 32. Double-buffered smem bf16 planes Ah/Al/Bh/Bl.
// modes: 0 logits fp32 out | 1 q/k conv (bias[col], packed out, z&1 selects)
//        2 v conv (bias[row], packed out) | 3 output fp32 out
// ---------------------------------------------------------------------------
#define KC     32
#define PLANE  8192                 // 128 rows * 64B
#define STAGE  (4 * PLANE)          // Ah, Al, Bh, Bl
#define SMEM_TOTAL (2 * STAGE)      // 65536

#define LDGALL(c)                                                              \
    do {                                                                       \
        const uint4* qa0 = (const uint4*)(pA0 + (long)(c) * KC);               \
        const uint4* qa1 = (const uint4*)(pA1 + (long)(c) * KC);               \
        const uint4* qb0 = (const uint4*)(pB0 + (long)(c) * KC);               \
        const uint4* qb1 = (const uint4*)(pB1 + (long)(c) * KC);               \
        rg[0] = qa0[0]; rg[1] = qa0[1];                                        \
        rg[2] = qa1[0]; rg[3] = qa1[1];                                        \
        rg[4] = qb0[0]; rg[5] = qb0[1];                                        \
        rg[6] = qb1[0]; rg[7] = qb1[1];                                        \
    } while (0)

#define SPLIT_STS(hiaddr, loaddr, p0, p1)                                      \
    do {                                                                       \
        sts128(hiaddr, __byte_perm((p0).x, (p0).y, 0x7632),                    \
                       __byte_perm((p0).z, (p0).w, 0x7632),                    \
                       __byte_perm((p1).x, (p1).y, 0x7632),                    \
                       __byte_perm((p1).z, (p1).w, 0x7632));                   \
        sts128(loaddr, __byte_perm((p0).x, (p0).y, 0x5410),                    \
                       __byte_perm((p0).z, (p0).w, 0x5410),                    \
                       __byte_perm((p1).x, (p1).y, 0x5410),                    \
                       __byte_perm((p1).z, (p1).w, 0x5410));                   \
    } while (0)

#define STSALL(sb)                                                             \
    do {                                                                       \
        SPLIT_STS((sb) + oA0,             (sb) + PLANE + oA0, rg[0], rg[1]);   \
        SPLIT_STS((sb) + oA1,             (sb) + PLANE + oA1, rg[2], rg[3]);   \
        SPLIT_STS((sb) + 2 * PLANE + oB0, (sb) + 3 * PLANE + oB0, rg[4], rg[5]); \
        SPLIT_STS((sb) + 2 * PLANE + oB1, (sb) + 3 * PLANE + oB1, rg[6], rg[7]); \
    } while (0)

__global__ __launch_bounds__(256, 1)
void gemm_mma(const uint32_t* __restrict__ A, long sA, int lda,
              const uint32_t* __restrict__ B, long sB, int ldb,
              const uint32_t* __restrict__ Balt,
              int K, int mode,
              float* __restrict__ Cf, long sCf, int ldc,
              uint32_t* __restrict__ Cp, uint32_t* __restrict__ Cp2,
              long sCp, int ldcp,
              const float* __restrict__ bias0, const float* __restrict__ bias1)
{
    extern __shared__ __align__(128) unsigned char smem[];
    const uint32_t sbase = smem_u32(smem);

    const int tid = threadIdx.x;
    const int lid = tid & 31;
    const int wid = tid >> 5;
    const int warp_m = wid >> 2;          // 0..1  -> m offset *64
    const int warp_n = wid & 3;           // 0..3  -> n offset *32

    int bz = blockIdx.z, b, wsel = 0;
    if (mode == 1) { b = bz >> 1; wsel = bz & 1; } else { b = bz; }

    const uint32_t* Ab = A + (long)b * sA;
    const uint32_t* Bb = (mode == 1) ? (wsel ? Balt : B) : (B + (long)b * sB);
    const float* bias = (mode == 1) ? (wsel ? bias1 : bias0) : bias0;

    const int bm = blockIdx.y * 128;
    const int bn = blockIdx.x * 128;

    // ---- loader mapping: 2 segs of 8 u32 per operand per thread ----
    const int s0 = tid, s1 = tid + 256;
    const int ra0 = s0 >> 2, ka0 = (s0 & 3) * 8;
    const int ra1 = s1 >> 2, ka1 = (s1 & 3) * 8;
    const uint32_t* pA0 = Ab + (long)(bm + ra0) * lda + ka0;
    const uint32_t* pA1 = Ab + (long)(bm + ra1) * lda + ka1;
    const uint32_t* pB0 = Bb + (long)(bn + ra0) * ldb + ka0;
    const uint32_t* pB1 = Bb + (long)(bn + ra1) * ldb + ka1;
    const uint32_t oA0 = SWZ64((uint32_t)(ra0 * 64 + ka0 * 2));
    const uint32_t oA1 = SWZ64((uint32_t)(ra1 * 64 + ka1 * 2));
    const uint32_t oB0 = oA0;   // same (row,k) mapping
    const uint32_t oB1 = oA1;

    float acc[4][4][4];
#pragma unroll
    for (int i = 0; i < 4; i++)
#pragma unroll
        for (int j = 0; j < 4; j++)
#pragma unroll
            for (int r = 0; r < 4; r++) acc[i][j][r] = 0.f;

    const int nchunk = K / KC;
    uint4 rg[8];

    // prologue: chunk 0 -> stage 0
    LDGALL(0);
    STSALL(sbase);
    __syncthreads();

    const int sub = lid >> 3, l7 = lid & 7;

    for (int c = 0; c < nchunk; c++) {
        if (c + 1 < nchunk) LDGALL(c + 1);

        const uint32_t sb = sbase + (uint32_t)(c & 1) * STAGE;
        const uint32_t Ah = sb, Al = sb + PLANE;
        const uint32_t Bh = sb + 2 * PLANE, Bl = sb + 3 * PLANE;

#pragma unroll
        for (int ks = 0; ks < 2; ks++) {
            // A frags: octets (m0-7,k0)(m8-15,k0)(m0-7,k8)(m8-15,k8)
            uint32_t ah[4][4], al[4][4];
            const int arow = warp_m * 64 + (sub & 1) * 8 + l7;
            const int akb  = ks * 16 + (sub >> 1) * 8;
#pragma unroll
            for (int i = 0; i < 4; i++) {
                const uint32_t off = SWZ64((uint32_t)((arow + i * 16) * 64 + akb * 2));
                ldsm4(ah[i][0], ah[i][1], ah[i][2], ah[i][3], Ah + off);
                ldsm4(al[i][0], al[i][1], al[i][2], al[i][3], Al + off);
            }
            // B frags: octets (n0-7,k0)(n0-7,k8)(n8-15,k0)(n8-15,k8)
            uint32_t bh[4][2], bl[4][2];
            const int brow = warp_n * 32 + (sub >> 1) * 8 + l7;
            const int bkb  = ks * 16 + (sub & 1) * 8;
#pragma unroll
            for (int g = 0; g < 2; g++) {
                const uint32_t off = SWZ64((uint32_t)((brow + g * 16) * 64 + bkb * 2));
                ldsm4(bh[2 * g][0], bh[2 * g][1], bh[2 * g + 1][0], bh[2 * g + 1][1],
                      Bh + off);
                ldsm4(bl[2 * g][0], bl[2 * g][1], bl[2 * g + 1][0], bl[2 * g + 1][1],
                      Bl + off);
            }
#pragma unroll
            for (int i = 0; i < 4; i++)
#pragma unroll
                for (int j = 0; j < 4; j++) {
                    mma16816(acc[i][j], ah[i], bh[j]);
                    mma16816(acc[i][j], ah[i], bl[j]);
                    mma16816(acc[i][j], al[i], bh[j]);
                }
        }

        if (c + 1 < nchunk)
            STSALL(sbase + (uint32_t)((c + 1) & 1) * STAGE);
        __syncthreads();
    }

    // ---- epilogue ----
#pragma unroll
    for (int i = 0; i < 4; i++)
#pragma unroll
        for (int j = 0; j < 4; j++) {
            const int m = bm + warp_m * 64 + i * 16 + (lid >> 2);
            const int n = bn + warp_n * 32 + j * 8 + (lid & 3) * 2;
            const float d0 = acc[i][j][0], d1 = acc[i][j][1];
            const float d2 = acc[i][j][2], d3 = acc[i][j][3];
            if (mode == 0 || mode == 3) {
                float* base = Cf + (long)b * sCf;
                *(float2*)(base + (long)m * ldc + n)       = make_float2(d0, d1);
                *(float2*)(base + (long)(m + 8) * ldc + n) = make_float2(d2, d3);
            } else if (mode == 1) {
                uint32_t* dst = (wsel ? Cp2 : Cp) + (long)b * sCp;
                const float bn0 = bias[n], bn1 = bias[n + 1];
                uint2 v0 = make_uint2(pack_split(d0 + bn0), pack_split(d1 + bn1));
                uint2 v1 = make_uint2(pack_split(d2 + bn0), pack_split(d3 + bn1));
                *(uint2*)(dst + (long)m * ldcp + n)       = v0;
                *(uint2*)(dst + (long)(m + 8) * ldcp + n) = v1;
            } else { // mode 2: bias over rows, packed out only
                const float bm0 = bias[m], bm8 = bias[m + 8];
                uint32_t* bp = Cp + (long)b * sCp;
                *(uint2*)(bp + (long)m * ldcp + n) =
                    make_uint2(pack_split(d0 + bm0), pack_split(d1 + bm0));
                *(uint2*)(bp + (long)(m + 8) * ldcp + n) =
                    make_uint2(pack_split(d2 + bm8), pack_split(d3 + bm8));
            }
        }
}

// ---------------------------------------------------------------------------
// Softmax over rows of att (fp32 in), writes packed split u32 IN PLACE.
// ---------------------------------------------------------------------------
__global__ __launch_bounds__(256)
void softmax_pack(float* __restrict__ att)
{
    const long row = blockIdx.x;
    float* p = att + row * NPIX;
    uint32_t* pu = (uint32_t*)p;
    __shared__ float red[256];
    const int t = threadIdx.x;

    float vals[9];
    float m = -INFINITY;
#pragma unroll
    for (int i = 0; i < 9; i++) {
        vals[i] = p[t + i * 256];
        m = fmaxf(m, vals[i]);
    }
    red[t] = m; __syncthreads();
    for (int s = 128; s > 0; s >>= 1) {
        if (t < s) red[t] = fmaxf(red[t], red[t + s]);
        __syncthreads();
    }
    m = red[0]; __syncthreads();

    float sum = 0.f;
#pragma unroll
    for (int i = 0; i < 9; i++) {
        vals[i] = __expf(vals[i] - m);
        sum += vals[i];
    }
    red[t] = sum; __syncthreads();
    for (int s = 128; s > 0; s >>= 1) {
        if (t < s) red[t] += red[t + s];
        __syncthreads();
    }
    const float inv = 1.f / red[0];
#pragma unroll
    for (int i = 0; i < 9; i++)
        pu[t + i * 256] = pack_split(vals[i] * inv);
}

// ---------------------------------------------------------------------------
// Final epilogue: out[b][e][n] = outT[b][n][e] + unpack(vP[b][e][n])
// ---------------------------------------------------------------------------
__global__ void epilogue_kernel(const float* __restrict__ outT,
                                const uint32_t* __restrict__ vP,
                                float* __restrict__ out)
{
    __shared__ float tile[32][33];
    const int b = blockIdx.z;
    const float*    src = outT + (long)b * NPIX * EMB;   // [N][E]
    const uint32_t* vb  = vP   + (long)b * EMB  * NPIX;  // [E][N] packed
    float*          ob  = out  + (long)b * EMB  * NPIX;  // [E][N]
    const int e0 = blockIdx.x * 32;
    const int n0 = blockIdx.y * 32;
    const int tx = threadIdx.x, ty = threadIdx.y;        // 32 x 8
#pragma unroll
    for (int i = 0; i < 32; i += 8)
        tile[ty + i][tx] = src[(long)(n0 + ty + i) * EMB + (e0 + tx)];
    __syncthreads();
#pragma unroll
    for (int i = 0; i < 32; i += 8) {
        long o = (long)(e0 + ty + i) * NPIX + (n0 + tx);
        ob[o] = tile[tx][ty + i] + unpack_split(vb[o]);
    }
}

// ---------------------------------------------------------------------------
// launch
// ---------------------------------------------------------------------------
extern "C" void kernel_launch(void* const* d_in, const int* in_sizes, int n_in,
                              void* d_out, int out_size)
{
    const float* feat = (const float*)d_in[0];
    const float* Wq   = (const float*)d_in[1];
    const float* bq   = (const float*)d_in[2];
    const float* Wk   = (const float*)d_in[3];
    const float* bk   = (const float*)d_in[4];
    const float* Wv   = (const float*)d_in[5];
    const float* bv   = (const float*)d_in[6];
    float* out = (float*)d_out;

    unsigned char* base;
    cudaGetSymbolAddress((void**)&base, g_scratch);
    uint32_t* colT = (uint32_t*)(base + OFF_COL);
    uint32_t* wqP  = (uint32_t*)(base + OFF_WQ);
    uint32_t* wkP  = (uint32_t*)(base + OFF_WK);
    uint32_t* wvP  = (uint32_t*)(base + OFF_WV);
    uint32_t* qT   = (uint32_t*)(base + OFF_QT);
    uint32_t* kT   = (uint32_t*)(base + OFF_KT);
    uint32_t* vP   = (uint32_t*)(base + OFF_VP);
    float*    att  = (float*)   (base + OFF_COL);   // alias; colT dead by then
    float*    outT = (float*)   (base + OFF_QT);    // alias; qT dead by then

    cudaFuncSetAttribute(gemm_mma, cudaFuncAttributeMaxDynamicSharedMemorySize,
                         SMEM_TOTAL);

    // 1) pack weights + build packed im2col
    {
        long n = (long)EMB * KDIM;
        pack_weights<<<(unsigned)((n + 255) / 256), 256>>>(Wq, Wk, Wv, wqP, wkP, wvP);
        long total = (long)BATCH * NPIX * KDIM;
        build_colT<<<(unsigned)((total + 255) / 256), 256>>>(feat, colT);
    }

    const long colS = (long)NPIX * KDIM;
    const long qtS  = (long)NPIX * EMB;
    const long attS = (long)NPIX * NPIX;

    // 2) q,k conv: D[n][e] = colT[n][:] . W[e][:] + bias[e]  (packed out)
    {
        dim3 grid(EMB / 128, NPIX / 128, 2 * BATCH);
        gemm_mma<<<grid, 256, SMEM_TOTAL>>>(colT, colS, KDIM,
                                            wqP, 0, KDIM, wkP,
                                            KDIM, 1,
                                            nullptr, 0, 0,
                                            qT, kT, qtS, EMB,
                                            bq, bk);
    }
    // 3) v conv: D[e][n] = W[e][:] . colT[n][:] + bias[e]  (packed out)
    {
        dim3 grid(NPIX / 128, EMB / 128, BATCH);
        gemm_mma<<<grid, 256, SMEM_TOTAL>>>(wvP, 0, KDIM,
                                            colT, colS, KDIM, nullptr,
                                            KDIM, 2,
                                            nullptr, 0, 0,
                                            vP, nullptr, qtS, NPIX,
                                            bv, nullptr);
    }
    // 4) logits: att[i][j] = qT[i][:] . kT[j][:]  (K=512, fp32 out)
    {
        dim3 grid(NPIX / 128, NPIX / 128, BATCH);
        gemm_mma<<<grid, 256, SMEM_TOTAL>>>(qT, qtS, EMB,
                                            kT, qtS, EMB, nullptr,
                                            EMB, 0,
                                            att, attS, NPIX,
                                            nullptr, nullptr, 0, 0,
                                            nullptr, nullptr);
    }
    // 5) softmax rows + pack in place
    softmax_pack<<<BATCH * NPIX, 256>>>(att);

    // 6) output: outT[i][e] = att[i][:] . vP[e][:]  (K=2304, fp32 out)
    {
        dim3 grid(EMB / 128, NPIX / 128, BATCH);
        gemm_mma<<<grid, 256, SMEM_TOTAL>>>((uint32_t*)att, attS, NPIX,
                                            vP, qtS, NPIX, nullptr,
                                            NPIX, 3,
                                            outT, qtS, EMB,
                                            nullptr, nullptr, 0, 0,
                                            nullptr, nullptr);
    }
    // 7) residual + transpose
    {
        dim3 grid(EMB / 32, NPIX / 32, BATCH);
        epilogue_kernel<<<grid, dim3(32, 8)>>>(outT, vP, out);
    }
}